// round 2
// baseline (speedup 1.0000x reference)
#include <cuda_runtime.h>
#include <cstdint>

// Problem constants
#define N_ 64
#define L_ 512
#define T_ 128
#define D_ 1024

// Scratch (device globals: allocation-free per harness rules)
__device__ float g_s1[N_ * L_];
__device__ float g_p [N_ * L_];

// ---------------------------------------------------------------------------
// Kernel 1: s1[n,l] = dot(f1[n,l,:], w).  One warp per row, 8 warps/block.
// ---------------------------------------------------------------------------
__global__ void __launch_bounds__(256) scores_kernel(
    const float* __restrict__ f1, const float* __restrict__ w)
{
    __shared__ float4 wsh[D_ / 4];  // 4 KB
    int tid = threadIdx.x;
    if (tid < D_ / 4) wsh[tid] = reinterpret_cast<const float4*>(w)[tid];
    __syncthreads();

    int warp = tid >> 5;
    int lane = tid & 31;
    int row  = blockIdx.x * 8 + warp;            // row in [0, N_*L_)
    const float4* r = reinterpret_cast<const float4*>(f1) + (size_t)row * (D_ / 4);

    float acc = 0.f;
#pragma unroll
    for (int i = 0; i < 8; ++i) {
        float4 a = r[lane + i * 32];
        float4 b = wsh[lane + i * 32];
        acc += a.x * b.x + a.y * b.y + a.z * b.z + a.w * b.w;
    }
#pragma unroll
    for (int o = 16; o > 0; o >>= 1)
        acc += __shfl_xor_sync(0xffffffffu, acc, o);

    if (lane == 0) g_s1[row] = acc;
}

// ---------------------------------------------------------------------------
// Kernel 2: per-n softmax over L=512, store p and broadcast-write att[n,t,l].
// 64 blocks x 512 threads.
// ---------------------------------------------------------------------------
__global__ void __launch_bounds__(512) softmax_kernel(float* __restrict__ att)
{
    __shared__ float red[16];
    int n = blockIdx.x;
    int l = threadIdx.x;
    int lane = l & 31, warp = l >> 5;

    float v = g_s1[n * L_ + l];

    // block max
    float m = v;
#pragma unroll
    for (int o = 16; o > 0; o >>= 1) m = fmaxf(m, __shfl_xor_sync(0xffffffffu, m, o));
    if (lane == 0) red[warp] = m;
    __syncthreads();
    if (warp == 0) {
        float x = red[lane & 15];
#pragma unroll
        for (int o = 8; o > 0; o >>= 1) x = fmaxf(x, __shfl_xor_sync(0xffffffffu, x, o));
        if (lane == 0) red[0] = x;
    }
    __syncthreads();
    m = red[0];
    __syncthreads();

    float e = __expf(v - m);

    // block sum
    float s = e;
#pragma unroll
    for (int o = 16; o > 0; o >>= 1) s += __shfl_xor_sync(0xffffffffu, s, o);
    if (lane == 0) red[warp] = s;
    __syncthreads();
    if (warp == 0) {
        float x = red[lane & 15];
#pragma unroll
        for (int o = 8; o > 0; o >>= 1) x += __shfl_xor_sync(0xffffffffu, x, o);
        if (lane == 0) red[0] = x;
    }
    __syncthreads();
    float p = e / red[0];

    g_p[n * L_ + l] = p;

    // att[n,t,l] = p for all t  (coalesced 2 KB rows)
    float* dst = att + (size_t)n * T_ * L_ + l;
#pragma unroll 4
    for (int t = 0; t < T_; ++t) dst[t * L_] = p;
}

// ---------------------------------------------------------------------------
// Kernel 3: g[n,d] = sum_l p[n,l] * f1[n,l,d];  f_hat[n,t,:] = g[n,:] all t.
// Grid (2, 64): block handles 128 float4 columns (512 floats) of one n.
// ---------------------------------------------------------------------------
__global__ void __launch_bounds__(128) out_kernel(
    const float* __restrict__ f1, float* __restrict__ fhat)
{
    __shared__ float psh[L_];
    int n = blockIdx.y;
    int c = blockIdx.x;  // 0 or 1

    for (int i = threadIdx.x; i < L_; i += 128) psh[i] = g_p[n * L_ + i];
    __syncthreads();

    int col4 = c * 128 + threadIdx.x;  // float4 column index in [0, 256)
    const float4* base = reinterpret_cast<const float4*>(f1)
                         + (size_t)n * L_ * (D_ / 4) + col4;

    float4 acc = make_float4(0.f, 0.f, 0.f, 0.f);
#pragma unroll 4
    for (int l = 0; l < L_; ++l) {
        float pv = psh[l];
        float4 a = base[(size_t)l * (D_ / 4)];
        acc.x = fmaf(pv, a.x, acc.x);
        acc.y = fmaf(pv, a.y, acc.y);
        acc.z = fmaf(pv, a.z, acc.z);
        acc.w = fmaf(pv, a.w, acc.w);
    }

    float4* o = reinterpret_cast<float4*>(fhat) + (size_t)n * T_ * (D_ / 4) + col4;
#pragma unroll 4
    for (int t = 0; t < T_; ++t) o[(size_t)t * (D_ / 4)] = acc;
}

// ---------------------------------------------------------------------------
extern "C" void kernel_launch(void* const* d_in, const int* in_sizes, int n_in,
                              void* d_out, int out_size)
{
    const float* f1 = (const float*)d_in[0];  // [N,L,D]
    // d_in[1] = feature_2 : unused (softmax shift-invariance cancels it)
    const float* w  = (const float*)d_in[2];  // [D]
    // d_in[3] = b : unused (cancels in softmax)

    float* fhat = (float*)d_out;                         // [N,T,D]
    float* att  = (float*)d_out + (size_t)N_ * T_ * D_;  // [N,T,L]

    scores_kernel <<< (N_ * L_) / 8, 256 >>> (f1, w);
    softmax_kernel<<< N_, 512 >>> (att);
    out_kernel    <<< dim3(2, N_), 128 >>> (f1, fhat);
}

// round 3
// speedup vs baseline: 1.6518x; 1.6518x over previous
#include <cuda_runtime.h>
#include <cstdint>

// Problem constants
#define N_ 64
#define L_ 512
#define T_ 128
#define D_ 1024
#define LCHUNKS 4
#define LSUB (L_ / LCHUNKS)   // 128

// Scratch (device globals: allocation-free per harness rules)
__device__ float g_s1[N_ * L_];
__device__ float g_p [N_ * L_];
__device__ float g_part[LCHUNKS][N_][D_];   // 1 MB partial sums

// ---------------------------------------------------------------------------
// Kernel 1: s1[n,l] = dot(f1[n,l,:], w).  One warp per row, 8 warps/block.
// ---------------------------------------------------------------------------
__global__ void __launch_bounds__(256) scores_kernel(
    const float* __restrict__ f1, const float* __restrict__ w)
{
    __shared__ float4 wsh[D_ / 4];  // 4 KB
    int tid = threadIdx.x;
    if (tid < D_ / 4) wsh[tid] = reinterpret_cast<const float4*>(w)[tid];
    __syncthreads();

    int warp = tid >> 5;
    int lane = tid & 31;
    int row  = blockIdx.x * 8 + warp;            // row in [0, N_*L_)
    const float4* r = reinterpret_cast<const float4*>(f1) + (size_t)row * (D_ / 4);

    float acc0 = 0.f, acc1 = 0.f;
#pragma unroll
    for (int i = 0; i < 8; i += 2) {
        float4 a0 = r[lane + i * 32];
        float4 b0 = wsh[lane + i * 32];
        float4 a1 = r[lane + (i + 1) * 32];
        float4 b1 = wsh[lane + (i + 1) * 32];
        acc0 += a0.x * b0.x + a0.y * b0.y + a0.z * b0.z + a0.w * b0.w;
        acc1 += a1.x * b1.x + a1.y * b1.y + a1.z * b1.z + a1.w * b1.w;
    }
    float acc = acc0 + acc1;
#pragma unroll
    for (int o = 16; o > 0; o >>= 1)
        acc += __shfl_xor_sync(0xffffffffu, acc, o);

    if (lane == 0) g_s1[row] = acc;
}

// ---------------------------------------------------------------------------
// Kernel 2: per-n softmax over L=512, store p and broadcast-write att[n,t,l].
// ---------------------------------------------------------------------------
__global__ void __launch_bounds__(512) softmax_kernel(float* __restrict__ att)
{
    __shared__ float red[16];
    int n = blockIdx.x;
    int l = threadIdx.x;
    int lane = l & 31, warp = l >> 5;

    float v = g_s1[n * L_ + l];

    float m = v;
#pragma unroll
    for (int o = 16; o > 0; o >>= 1) m = fmaxf(m, __shfl_xor_sync(0xffffffffu, m, o));
    if (lane == 0) red[warp] = m;
    __syncthreads();
    if (warp == 0) {
        float x = red[lane & 15];
#pragma unroll
        for (int o = 8; o > 0; o >>= 1) x = fmaxf(x, __shfl_xor_sync(0xffffffffu, x, o));
        if (lane == 0) red[0] = x;
    }
    __syncthreads();
    m = red[0];
    __syncthreads();

    float e = __expf(v - m);

    float s = e;
#pragma unroll
    for (int o = 16; o > 0; o >>= 1) s += __shfl_xor_sync(0xffffffffu, s, o);
    if (lane == 0) red[warp] = s;
    __syncthreads();
    if (warp == 0) {
        float x = red[lane & 15];
#pragma unroll
        for (int o = 8; o > 0; o >>= 1) x += __shfl_xor_sync(0xffffffffu, x, o);
        if (lane == 0) red[0] = x;
    }
    __syncthreads();
    float p = e / red[0];

    g_p[n * L_ + l] = p;

    float* dst = att + (size_t)n * T_ * L_ + l;
#pragma unroll 4
    for (int t = 0; t < T_; ++t) dst[t * L_] = p;
}

// ---------------------------------------------------------------------------
// Kernel 3a: partial reduction over an L-chunk.
// Grid (cchunk=2, lchunk=4, n=64) = 512 CTAs, 128 threads.
// g_part[lc][n][col] = sum_{l in chunk} p[n,l] * f1[n,l,col]
// ---------------------------------------------------------------------------
__global__ void __launch_bounds__(128) out_partial_kernel(
    const float* __restrict__ f1)
{
    __shared__ float psh[LSUB];
    int c  = blockIdx.x;   // 0..1   column half
    int lc = blockIdx.y;   // 0..3   L chunk
    int n  = blockIdx.z;   // 0..63

    if (threadIdx.x < LSUB) psh[threadIdx.x] = g_p[n * L_ + lc * LSUB + threadIdx.x];
    __syncthreads();

    int col4 = c * 128 + threadIdx.x;  // float4 column index in [0, 256)
    const float4* base = reinterpret_cast<const float4*>(f1)
                         + (size_t)n * L_ * (D_ / 4)
                         + (size_t)lc * LSUB * (D_ / 4) + col4;

    float4 acc = make_float4(0.f, 0.f, 0.f, 0.f);
#pragma unroll 8
    for (int l = 0; l < LSUB; ++l) {
        float pv = psh[l];
        float4 a = base[(size_t)l * (D_ / 4)];
        acc.x = fmaf(pv, a.x, acc.x);
        acc.y = fmaf(pv, a.y, acc.y);
        acc.z = fmaf(pv, a.z, acc.z);
        acc.w = fmaf(pv, a.w, acc.w);
    }

    reinterpret_cast<float4*>(&g_part[lc][n][0])[col4] = acc;
}

// ---------------------------------------------------------------------------
// Kernel 3b: sum 4 partials, broadcast across T.
// Grid (n=64, tchunk=8) = 512 CTAs, 256 threads. Each thread owns 1 float4
// column and writes 16 t-rows.
// ---------------------------------------------------------------------------
__global__ void __launch_bounds__(256) out_bcast_kernel(
    float* __restrict__ fhat)
{
    int n  = blockIdx.x;
    int tc = blockIdx.y;   // 0..7
    int col4 = threadIdx.x;  // 0..255

    float4 a = reinterpret_cast<const float4*>(&g_part[0][n][0])[col4];
    float4 b = reinterpret_cast<const float4*>(&g_part[1][n][0])[col4];
    float4 cc = reinterpret_cast<const float4*>(&g_part[2][n][0])[col4];
    float4 d = reinterpret_cast<const float4*>(&g_part[3][n][0])[col4];
    float4 acc;
    acc.x = (a.x + b.x) + (cc.x + d.x);
    acc.y = (a.y + b.y) + (cc.y + d.y);
    acc.z = (a.z + b.z) + (cc.z + d.z);
    acc.w = (a.w + b.w) + (cc.w + d.w);

    float4* o = reinterpret_cast<float4*>(fhat)
                + (size_t)n * T_ * (D_ / 4)
                + (size_t)tc * (T_ / 8) * (D_ / 4) + col4;
#pragma unroll
    for (int t = 0; t < T_ / 8; ++t)
        o[(size_t)t * (D_ / 4)] = acc;
}

// ---------------------------------------------------------------------------
extern "C" void kernel_launch(void* const* d_in, const int* in_sizes, int n_in,
                              void* d_out, int out_size)
{
    const float* f1 = (const float*)d_in[0];  // [N,L,D]
    // d_in[1] = feature_2 : unused (softmax shift-invariance cancels it)
    const float* w  = (const float*)d_in[2];  // [D]
    // d_in[3] = b : unused (cancels in softmax)

    float* fhat = (float*)d_out;                         // [N,T,D]
    float* att  = (float*)d_out + (size_t)N_ * T_ * D_;  // [N,T,L]

    scores_kernel     <<< (N_ * L_) / 8, 256 >>> (f1, w);
    softmax_kernel    <<< N_, 512 >>> (att);
    out_partial_kernel<<< dim3(2, LCHUNKS, N_), 128 >>> (f1);
    out_bcast_kernel  <<< dim3(N_, 8), 256 >>> (fhat);
}